// round 13
// baseline (speedup 1.0000x reference)
#include <cuda_runtime.h>

#define NN 50000
#define EE 1600000
#define H  64
#define STEAL (EE/32)   // 50000 steal units of 32 edges (4 x 8-edge subtiles)

typedef unsigned long long ull;

// ---------------- scratch (device globals; no allocation allowed) ----------------
__device__ float g_h[NN*H];
__device__ float g_A[NN*H];      // h@Wa + e_b1
__device__ float g_B[NN*H];      // h@Wb
__device__ float g_magg[NN*H];   // segment-summed messages
__device__ float g_cagg4[NN*4];  // segment-summed coord updates (padded)
__device__ float g_vel[NN];      // vel_scale
__device__ float g_deg[NN];      // clipped out-degree (float)
__device__ int   g_cnt[NN];      // raw out-degree
__device__ int   g_off[NN];      // fill cursors
__device__ float g_x4[NN*4];     // padded coords
__device__ float g_v4[NN*4];     // padded velocities
__device__ int   g_tile;         // dynamic steal cursor
// r-sorted edge arrays
__device__ int    g_er[EE];
__device__ int    g_ec[EE];
__device__ float2 g_ea2[EE];

__device__ __forceinline__ float silu_f(float x){
    float th;
    asm("tanh.approx.f32 %0, %1;" : "=f"(th) : "f"(0.5f*x));
    return 0.5f*x*th + 0.5f*x;
}
__device__ __forceinline__ ull pack2(float x, float y){
    ull r; asm("mov.b64 %0, {%1,%2};" : "=l"(r) : "f"(x), "f"(y)); return r;
}
__device__ __forceinline__ float2 unpack2(ull p){
    float2 r; asm("mov.b64 {%0,%1}, %2;" : "=f"(r.x), "=f"(r.y) : "l"(p)); return r;
}
__device__ __forceinline__ void fma2(ull& d, ull a, ull b){
    asm("fma.rn.f32x2 %0, %1, %2, %0;" : "+l"(d) : "l"(a), "l"(b));
}
__device__ __forceinline__ void red4(float* p, float a, float b, float c, float d){
    asm volatile("red.global.add.v4.f32 [%0], {%1,%2,%3,%4};"
                 :: "l"(p), "f"(a), "f"(b), "f"(c), "f"(d) : "memory");
}

// ---------------- init ------------------------------------------------------------
__global__ void k_init(const float* __restrict__ his, const float* __restrict__ emb_w,
                       const float* __restrict__ emb_b, const float* __restrict__ x,
                       const float* __restrict__ v){
    int idx = blockIdx.x*blockDim.x + threadIdx.x;
    if (idx < NN*H){
        int n = idx >> 6, j = idx & 63;
        float acc = emb_b[j];
        #pragma unroll
        for (int k=0;k<16;k++) acc += his[n*16+k]*emb_w[k*H+j];
        g_h[idx] = acc;
    }
    if (idx < NN){
        g_x4[idx*4+0]=x[idx*3+0]; g_x4[idx*4+1]=x[idx*3+1]; g_x4[idx*4+2]=x[idx*3+2]; g_x4[idx*4+3]=0.f;
        g_v4[idx*4+0]=v[idx*3+0]; g_v4[idx*4+1]=v[idx*3+1]; g_v4[idx*4+2]=v[idx*3+2]; g_v4[idx*4+3]=0.f;
        g_cnt[idx] = 0;
    }
}

__global__ void k_deg(const int* __restrict__ edges){
    int e = blockIdx.x*blockDim.x + threadIdx.x;
    if (e < EE) atomicAdd(&g_cnt[edges[e]], 1);
}

// single-block exclusive scan over g_cnt -> g_off; also g_deg = max(cnt,1)
__global__ void k_scan(){
    __shared__ int s_part[1024];
    int tid = threadIdx.x;
    const int CH = (NN + 1023)/1024;
    int base = tid*CH;
    int sum = 0;
    #pragma unroll 7
    for (int i=0;i<CH;i++){ int n=base+i; if(n<NN) sum += g_cnt[n]; }
    s_part[tid] = sum;
    __syncthreads();
    for (int off=1; off<1024; off<<=1){
        int t = (tid >= off) ? s_part[tid-off] : 0;
        __syncthreads();
        s_part[tid] += t;
        __syncthreads();
    }
    int run = s_part[tid] - sum;
    for (int i=0;i<CH;i++){
        int n = base+i;
        if (n < NN){
            int c = g_cnt[n];
            g_off[n] = run;
            g_deg[n] = (c > 0) ? (float)c : 1.0f;
            run += c;
        }
    }
}

__global__ void k_fill(const int* __restrict__ edges, const float* __restrict__ edge_attr){
    int e = blockIdx.x*blockDim.x + threadIdx.x;
    if (e < EE){
        int r = edges[e];
        int pos = atomicAdd(&g_off[r], 1);
        g_er[pos] = r;
        g_ec[pos] = edges[EE+e];
        g_ea2[pos] = ((const float2*)edge_attr)[e];
    }
}

// ------ per-layer node precompute: A,B, vel_scale; zero aggs; reset cursor --------
__global__ void k_prevel(const float* __restrict__ e_w1, const float* __restrict__ e_b1,
                         const float* __restrict__ v_w1, const float* __restrict__ v_b1,
                         const float* __restrict__ v_w2, const float* __restrict__ v_b2){
    extern __shared__ float sp[];
    float* s_ew  = sp;
    float* s_vw  = sp + 8192;
    float* s_eb1 = sp + 12288;
    float* s_vb1 = sp + 12352;
    float* s_vw2 = sp + 12416;
    int tid = threadIdx.x;
    if (blockIdx.x == 0 && tid == 0) g_tile = 0;
    for (int i=tid; i<8192; i+=blockDim.x) s_ew[i] = e_w1[i];
    for (int i=tid; i<4096; i+=blockDim.x) s_vw[i] = v_w1[i];
    if (tid < 64){ s_eb1[tid]=e_b1[tid]; s_vb1[tid]=v_b1[tid]; s_vw2[tid]=v_w2[tid]; }
    __syncthreads();
    int lane = tid & 31, warp = tid >> 5;
    int j0 = 2*lane;
    int wpb = blockDim.x >> 5;
    float vb2 = v_b2[0];
    for (int n = blockIdx.x*wpb + warp; n < NN; n += gridDim.x*wpb){
        float h0 = g_h[n*H+j0], h1 = g_h[n*H+j0+1];
        float a0 = s_eb1[j0], a1 = s_eb1[j0+1];
        float b0 = 0.f, b1 = 0.f;
        float t0 = s_vb1[j0], t1 = s_vb1[j0+1];
        #pragma unroll
        for (int k=0;k<H;k++){
            float hk = __shfl_sync(0xffffffffu, (k&1)?h1:h0, k>>1);
            float2 wa = *(const float2*)&s_ew[k*H+j0];
            float2 wb = *(const float2*)&s_ew[(H+k)*H+j0];
            float2 wv = *(const float2*)&s_vw[k*H+j0];
            a0 += hk*wa.x; a1 += hk*wa.y;
            b0 += hk*wb.x; b1 += hk*wb.y;
            t0 += hk*wv.x; t1 += hk*wv.y;
        }
        *(float2*)&g_A[n*H+j0]    = make_float2(a0,a1);
        *(float2*)&g_B[n*H+j0]    = make_float2(b0,b1);
        *(float2*)&g_magg[n*H+j0] = make_float2(0.f,0.f);
        float p = silu_f(t0)*s_vw2[j0] + silu_f(t1)*s_vw2[j0+1];
        #pragma unroll
        for (int o=16;o>0;o>>=1) p += __shfl_xor_sync(0xffffffffu, p, o);
        if (lane == 0){
            g_vel[n] = p + vb2;
            *(float4*)&g_cagg4[n*4] = make_float4(0.f,0.f,0.f,0.f);
        }
    }
}

// ------- edge kernel: warp-autonomous 8-edge subtiles, 64-reg budget, 4 blocks/SM -
__global__ void __launch_bounds__(256, 4)
k_edge(const float* __restrict__ e_w1, const float* __restrict__ e_w2,
       const float* __restrict__ e_b2, const float* __restrict__ c_w1,
       const float* __restrict__ c_b1, const float* __restrict__ c_w2){
    extern __shared__ float sm[];
    float* s_w2  = sm;              // 4096 (block-shared, read-only)
    float* s_c1  = sm + 4096;       // 4096
    float* s_wr  = sm + 8192;       // 64
    float* s_we0 = sm + 8256;
    float* s_we1 = sm + 8320;
    float* s_eb2 = sm + 8384;
    float* s_cb1 = sm + 8448;
    float* s_cw2 = sm + 8512;       // .. 8576
    int tid  = threadIdx.x;
    int wid  = tid >> 5, lane = tid & 31;
    float* wbp  = sm + 8576 + wid*544;    // per-warp region (544 floats)
    float* s_t  = wbp;                    // 64 x 8
    int*   s_r  = (int*)(wbp + 512);      // 8
    float* s_dx = wbp + 520;              // 8
    float* s_dy = wbp + 528;
    float* s_dz = wbp + 536;
    // total smem: 8576 + 8*544 = 12928 floats = 51712 B

    for (int i=tid; i<4096; i+=256){ s_w2[i] = e_w2[i]; s_c1[i] = c_w1[i]; }
    if (tid < 64){
        s_wr [tid] = e_w1[128*H+tid];
        s_we0[tid] = e_w1[129*H+tid];
        s_we1[tid] = e_w1[130*H+tid];
        s_eb2[tid] = e_b2[tid];
        s_cb1[tid] = c_b1[tid];
        s_cw2[tid] = c_w2[tid];
    }
    __syncthreads();

    const unsigned FM = 0xffffffffu;
    int el = lane & 7,  qh = lane >> 3;   // P1: 4 lanes/edge, each 16 k-values
    int eg = lane & 3,  og = lane >> 2;   // GEMMs: 2 edges x 8 outputs per lane

    int base = 0;
    if (lane == 0) base = atomicAdd(&g_tile, 1);
    base = __shfl_sync(FM, base, 0);

    while (base < STEAL){
        #pragma unroll 1
        for (int sub=0; sub<4; sub++){
            // ---- P1: gather + first-layer pre + silu -> s_t[k][e] ----
            {
                int e = base*32 + sub*8 + el;
                int r = g_er[e], c = g_ec[e];
                float4 xr = *(const float4*)&g_x4[r*4];
                float4 xc = *(const float4*)&g_x4[c*4];
                float dx = xr.x-xc.x, dy = xr.y-xc.y, dz = xr.z-xc.z;
                float radial = dx*dx + dy*dy + dz*dz;
                float2 ea = g_ea2[e];
                const float4* Ap = (const float4*)(g_A + r*H + qh*16);
                const float4* Bp = (const float4*)(g_B + c*H + qh*16);
                int kb = qh*16;
                #pragma unroll
                for (int q=0;q<4;q++){
                    float4 av = Ap[q], bv = Bp[q];
                    int k = kb + 4*q;
                    float4 w1 = *(const float4*)&s_wr [k];
                    float4 w2 = *(const float4*)&s_we0[k];
                    float4 w3 = *(const float4*)&s_we1[k];
                    s_t[(k+0)*8+el] = silu_f(av.x + bv.x + radial*w1.x + ea.x*w2.x + ea.y*w3.x);
                    s_t[(k+1)*8+el] = silu_f(av.y + bv.y + radial*w1.y + ea.x*w2.y + ea.y*w3.y);
                    s_t[(k+2)*8+el] = silu_f(av.z + bv.z + radial*w1.z + ea.x*w2.z + ea.y*w3.z);
                    s_t[(k+3)*8+el] = silu_f(av.w + bv.w + radial*w1.w + ea.x*w2.w + ea.y*w3.w);
                }
                if (!qh){ s_r[el]=r; s_dx[el]=dx; s_dy[el]=dy; s_dz[el]=dz; }
            }
            __syncwarp();

            // ---- P2: GEMM1  M[e][j] = sum_k t[k][e] * w2[k][j] ----
            ull acc[8];
            {
                ull b0 = *(const ull*)&s_eb2[og*8+0];
                ull b1 = *(const ull*)&s_eb2[og*8+2];
                ull b2 = *(const ull*)&s_eb2[og*8+4];
                ull b3 = *(const ull*)&s_eb2[og*8+6];
                acc[0]=b0; acc[1]=b1; acc[2]=b2; acc[3]=b3;
                acc[4]=b0; acc[5]=b1; acc[6]=b2; acc[7]=b3;
                const float* tp = s_t + eg*2;
                const float* wk = s_w2 + og*8;
                #pragma unroll 8
                for (int k=0;k<64;k++){
                    float2 tv = *(const float2*)(tp + k*8);
                    ulonglong2 wa = *(const ulonglong2*)(wk + k*64);
                    ulonglong2 wb = *(const ulonglong2*)(wk + k*64 + 4);
                    ull t0 = pack2(tv.x,tv.x), t1 = pack2(tv.y,tv.y);
                    fma2(acc[0], t0, wa.x); fma2(acc[1], t0, wa.y);
                    fma2(acc[2], t0, wb.x); fma2(acc[3], t0, wb.y);
                    fma2(acc[4], t1, wa.x); fma2(acc[5], t1, wa.y);
                    fma2(acc[6], t1, wb.x); fma2(acc[7], t1, wb.y);
                }
            }
            __syncwarp();   // all P2 reads of s_t done before P3 overwrites

            // ---- P3: silu(M), store ms -> s_t[j][e], run-agg scatter to m_agg ----
            {
                float ms[2][8];
                #pragma unroll
                for (int e2=0;e2<2;e2++){
                    #pragma unroll
                    for (int jp=0;jp<4;jp++){
                        float2 f = unpack2(acc[e2*4+jp]);
                        ms[e2][2*jp]   = silu_f(f.x);
                        ms[e2][2*jp+1] = silu_f(f.y);
                    }
                }
                #pragma unroll
                for (int j=0;j<8;j++){
                    *(float2*)&s_t[(og*8+j)*8 + eg*2] = make_float2(ms[0][j], ms[1][j]);
                }
                int r0 = s_r[eg*2], r1 = s_r[eg*2+1];
                if (r0 == r1){
                    #pragma unroll
                    for (int j=0;j<8;j++) ms[0][j] += ms[1][j];
                    float* mp = &g_magg[r0*H + og*8];
                    red4(mp,   ms[0][0], ms[0][1], ms[0][2], ms[0][3]);
                    red4(mp+4, ms[0][4], ms[0][5], ms[0][6], ms[0][7]);
                } else {
                    float* mp = &g_magg[r0*H + og*8];
                    red4(mp,   ms[0][0], ms[0][1], ms[0][2], ms[0][3]);
                    red4(mp+4, ms[0][4], ms[0][5], ms[0][6], ms[0][7]);
                    mp = &g_magg[r1*H + og*8];
                    red4(mp,   ms[1][0], ms[1][1], ms[1][2], ms[1][3]);
                    red4(mp+4, ms[1][4], ms[1][5], ms[1][6], ms[1][7]);
                }
            }
            __syncwarp();

            // ---- P4: GEMM2 + g partial; shfl-reduce over og; coord scatter ----
            {
                ull b0 = *(const ull*)&s_cb1[og*8+0];
                ull b1 = *(const ull*)&s_cb1[og*8+2];
                ull b2 = *(const ull*)&s_cb1[og*8+4];
                ull b3 = *(const ull*)&s_cb1[og*8+6];
                acc[0]=b0; acc[1]=b1; acc[2]=b2; acc[3]=b3;
                acc[4]=b0; acc[5]=b1; acc[6]=b2; acc[7]=b3;
                const float* tp = s_t + eg*2;
                const float* wk = s_c1 + og*8;
                #pragma unroll 8
                for (int k=0;k<64;k++){
                    float2 tv = *(const float2*)(tp + k*8);
                    ulonglong2 wa = *(const ulonglong2*)(wk + k*64);
                    ulonglong2 wb = *(const ulonglong2*)(wk + k*64 + 4);
                    ull t0 = pack2(tv.x,tv.x), t1 = pack2(tv.y,tv.y);
                    fma2(acc[0], t0, wa.x); fma2(acc[1], t0, wa.y);
                    fma2(acc[2], t0, wb.x); fma2(acc[3], t0, wb.y);
                    fma2(acc[4], t1, wa.x); fma2(acc[5], t1, wa.y);
                    fma2(acc[6], t1, wb.x); fma2(acc[7], t1, wb.y);
                }
                float gp0 = 0.f, gp1 = 0.f;
                #pragma unroll
                for (int jp=0;jp<4;jp++){
                    float2 f0 = unpack2(acc[jp]);
                    float2 f1 = unpack2(acc[4+jp]);
                    float w0 = s_cw2[og*8+2*jp], w1 = s_cw2[og*8+2*jp+1];
                    gp0 += silu_f(f0.x)*w0 + silu_f(f0.y)*w1;
                    gp1 += silu_f(f1.x)*w0 + silu_f(f1.y)*w1;
                }
                #pragma unroll
                for (int off=4; off<32; off<<=1){
                    gp0 += __shfl_xor_sync(FM, gp0, off);
                    gp1 += __shfl_xor_sync(FM, gp1, off);
                }
                if (og == 0){
                    int r0 = s_r[eg*2], r1 = s_r[eg*2+1];
                    float cx = s_dx[eg*2]*gp0, cy = s_dy[eg*2]*gp0, cz = s_dz[eg*2]*gp0;
                    float ex = s_dx[eg*2+1]*gp1, ey = s_dy[eg*2+1]*gp1, ez = s_dz[eg*2+1]*gp1;
                    if (r0 == r1){
                        red4(&g_cagg4[r0*4], cx+ex, cy+ey, cz+ez, 0.f);
                    } else {
                        red4(&g_cagg4[r0*4], cx, cy, cz, 0.f);
                        red4(&g_cagg4[r1*4], ex, ey, ez, 0.f);
                    }
                }
            }
            __syncwarp();   // protect s_t/s_r before next subtile's P1
        }
        if (lane == 0) base = atomicAdd(&g_tile, 1);
        base = __shfl_sync(FM, base, 0);
    }
}

// -------- fused node MLP + state update ------------------------------------------
__global__ void k_node(const float* __restrict__ n_w1, const float* __restrict__ n_b1,
                       const float* __restrict__ n_w2, const float* __restrict__ n_b2){
    extern __shared__ float sn[];
    float* s_w1 = sn;
    float* s_w2 = sn + 8192;
    float* s_b1 = sn + 12288;
    float* s_b2 = sn + 12352;
    int tid = threadIdx.x;
    for (int i=tid; i<8192; i+=blockDim.x) s_w1[i] = n_w1[i];
    for (int i=tid; i<4096; i+=blockDim.x) s_w2[i] = n_w2[i];
    if (tid < 64){ s_b1[tid]=n_b1[tid]; s_b2[tid]=n_b2[tid]; }
    __syncthreads();
    int lane = tid & 31, warp = tid >> 5;
    int j0 = 2*lane;
    int wpb = blockDim.x >> 5;
    for (int n = blockIdx.x*wpb + warp; n < NN; n += gridDim.x*wpb){
        float h0 = g_h[n*H+j0],    h1 = g_h[n*H+j0+1];
        float m0 = g_magg[n*H+j0], m1 = g_magg[n*H+j0+1];
        float u0 = s_b1[j0], u1 = s_b1[j0+1];
        #pragma unroll
        for (int k=0;k<H;k++){
            float hk = __shfl_sync(0xffffffffu, (k&1)?h1:h0, k>>1);
            float mk = __shfl_sync(0xffffffffu, (k&1)?m1:m0, k>>1);
            float2 wv1 = *(const float2*)&s_w1[k*H+j0];
            float2 wv2 = *(const float2*)&s_w1[(H+k)*H+j0];
            u0 += hk*wv1.x + mk*wv2.x;
            u1 += hk*wv1.y + mk*wv2.y;
        }
        u0 = silu_f(u0); u1 = silu_f(u1);
        float a0 = s_b2[j0], a1 = s_b2[j0+1];
        #pragma unroll
        for (int k=0;k<H;k++){
            float uk = __shfl_sync(0xffffffffu, (k&1)?u1:u0, k>>1);
            float2 wv = *(const float2*)&s_w2[k*H+j0];
            a0 += uk*wv.x; a1 += uk*wv.y;
        }
        *(float2*)&g_h[n*H+j0] = make_float2(2.f*h0 + a0, 2.f*h1 + a1);
        if (lane < 3){
            float dg = g_deg[n];
            float cm = g_cagg4[n*4+lane] / dg;
            float vi = g_v4[n*4+lane];
            float vn = vi + cm + g_vel[n]*vi;
            g_v4[n*4+lane] = vn;
            g_x4[n*4+lane] += vn;
        }
    }
}

// ---------------- output: [x | h | v] ---------------------------------------------
__global__ void k_out(float* __restrict__ out){
    int i = blockIdx.x*blockDim.x + threadIdx.x;
    if (i < NN*3){
        int n = i/3, d = i - n*3;
        out[i] = g_x4[n*4+d];
    } else if (i < NN*3+NN*H){
        out[i] = g_h[i-NN*3];
    } else if (i < NN*(6+H)){
        int j = i - NN*3 - NN*H;
        int n = j/3, d = j - n*3;
        out[i] = g_v4[n*4+d];
    }
}

extern "C" void kernel_launch(void* const* d_in, const int* in_sizes, int n_in,
                              void* d_out, int out_size){
    const float* his  = (const float*)d_in[0];
    const float* x    = (const float*)d_in[1];
    const float* v    = (const float*)d_in[2];
    const float* edge_attr = (const float*)d_in[3];
    const int*   edges= (const int*)  d_in[4];
    const float* emb_w= (const float*)d_in[5];
    const float* emb_b= (const float*)d_in[6];
    const float* e_w1 = (const float*)d_in[7];
    const float* e_b1 = (const float*)d_in[8];
    const float* e_w2 = (const float*)d_in[9];
    const float* e_b2 = (const float*)d_in[10];
    const float* c_w1 = (const float*)d_in[11];
    const float* c_b1 = (const float*)d_in[12];
    const float* c_w2 = (const float*)d_in[13];
    const float* n_w1 = (const float*)d_in[14];
    const float* n_b1 = (const float*)d_in[15];
    const float* n_w2 = (const float*)d_in[16];
    const float* n_b2 = (const float*)d_in[17];
    const float* v_w1 = (const float*)d_in[18];
    const float* v_b1 = (const float*)d_in[19];
    const float* v_w2 = (const float*)d_in[20];
    const float* v_b2 = (const float*)d_in[21];

    const int PREVEL_SMEM = 12480*4;
    const int NODE_SMEM   = 12416*4;
    const int EDGE_SMEM   = 12928*4;   // 51712 B
    cudaFuncSetAttribute(k_prevel, cudaFuncAttributeMaxDynamicSharedMemorySize, PREVEL_SMEM);
    cudaFuncSetAttribute(k_node,   cudaFuncAttributeMaxDynamicSharedMemorySize, NODE_SMEM);
    cudaFuncSetAttribute(k_edge,   cudaFuncAttributeMaxDynamicSharedMemorySize, EDGE_SMEM);

    k_init<<<(NN*H+255)/256, 256>>>(his, emb_w, emb_b, x, v);
    k_deg<<<(EE+255)/256, 256>>>(edges);
    k_scan<<<1, 1024>>>();
    k_fill<<<(EE+255)/256, 256>>>(edges, edge_attr);

    const int gn = 444;
    const int ge = 592;    // 148 SMs x 4 blocks; 32 autonomous warps/SM

    for (int l=0; l<3; l++){
        k_prevel<<<gn, 256, PREVEL_SMEM>>>(e_w1, e_b1, v_w1, v_b1, v_w2, v_b2);
        k_edge<<<ge, 256, EDGE_SMEM>>>(e_w1, e_w2, e_b2, c_w1, c_b1, c_w2);
        k_node<<<gn, 256, NODE_SMEM>>>(n_w1, n_b1, n_w2, n_b2);
    }
    k_out<<<(NN*(H+6)+255)/256, 256>>>((float*)d_out);
}

// round 14
// speedup vs baseline: 1.1688x; 1.1688x over previous
#include <cuda_runtime.h>

#define NN 50000
#define EE 1600000
#define H  64
#define STEAL (EE/32)   // 50000 steal units of 32 edges (2 x 16-edge subtiles)

typedef unsigned long long ull;

// ---------------- scratch (device globals; no allocation allowed) ----------------
__device__ float g_h[NN*H];
__device__ float g_A[NN*H];      // h@Wa + e_b1
__device__ float g_B[NN*H];      // h@Wb
__device__ float g_magg[NN*H];   // segment-summed messages
__device__ float g_cagg4[NN*4];  // segment-summed coord updates (padded)
__device__ float g_vel[NN];      // vel_scale
__device__ float g_deg[NN];      // clipped out-degree (float)
__device__ int   g_cnt[NN];      // raw out-degree
__device__ int   g_off[NN];      // fill cursors
__device__ float g_x4[NN*4];     // padded coords
__device__ float g_v4[NN*4];     // padded velocities
__device__ int   g_tile;         // dynamic steal cursor
// r-sorted edge arrays
__device__ int    g_er[EE];
__device__ int    g_ec[EE];
__device__ float2 g_ea2[EE];

__device__ __forceinline__ float silu_f(float x){
    float th;
    asm("tanh.approx.f32 %0, %1;" : "=f"(th) : "f"(0.5f*x));
    return 0.5f*x*th + 0.5f*x;
}
__device__ __forceinline__ ull pack2(float x, float y){
    ull r; asm("mov.b64 %0, {%1,%2};" : "=l"(r) : "f"(x), "f"(y)); return r;
}
__device__ __forceinline__ float2 unpack2(ull p){
    float2 r; asm("mov.b64 {%0,%1}, %2;" : "=f"(r.x), "=f"(r.y) : "l"(p)); return r;
}
__device__ __forceinline__ void fma2(ull& d, ull a, ull b){
    asm("fma.rn.f32x2 %0, %1, %2, %0;" : "+l"(d) : "l"(a), "l"(b));
}
__device__ __forceinline__ void red4(float* p, float a, float b, float c, float d){
    asm volatile("red.global.add.v4.f32 [%0], {%1,%2,%3,%4};"
                 :: "l"(p), "f"(a), "f"(b), "f"(c), "f"(d) : "memory");
}

// ---------------- init ------------------------------------------------------------
__global__ void k_init(const float* __restrict__ his, const float* __restrict__ emb_w,
                       const float* __restrict__ emb_b, const float* __restrict__ x,
                       const float* __restrict__ v){
    int idx = blockIdx.x*blockDim.x + threadIdx.x;
    if (idx < NN*H){
        int n = idx >> 6, j = idx & 63;
        float acc = emb_b[j];
        #pragma unroll
        for (int k=0;k<16;k++) acc += his[n*16+k]*emb_w[k*H+j];
        g_h[idx] = acc;
    }
    if (idx < NN){
        g_x4[idx*4+0]=x[idx*3+0]; g_x4[idx*4+1]=x[idx*3+1]; g_x4[idx*4+2]=x[idx*3+2]; g_x4[idx*4+3]=0.f;
        g_v4[idx*4+0]=v[idx*3+0]; g_v4[idx*4+1]=v[idx*3+1]; g_v4[idx*4+2]=v[idx*3+2]; g_v4[idx*4+3]=0.f;
        g_cnt[idx] = 0;
    }
}

__global__ void k_deg(const int* __restrict__ edges){
    int e = blockIdx.x*blockDim.x + threadIdx.x;
    if (e < EE) atomicAdd(&g_cnt[edges[e]], 1);
}

// single-block exclusive scan over g_cnt -> g_off; also g_deg = max(cnt,1)
__global__ void k_scan(){
    __shared__ int s_part[1024];
    int tid = threadIdx.x;
    const int CH = (NN + 1023)/1024;
    int base = tid*CH;
    int sum = 0;
    #pragma unroll 7
    for (int i=0;i<CH;i++){ int n=base+i; if(n<NN) sum += g_cnt[n]; }
    s_part[tid] = sum;
    __syncthreads();
    for (int off=1; off<1024; off<<=1){
        int t = (tid >= off) ? s_part[tid-off] : 0;
        __syncthreads();
        s_part[tid] += t;
        __syncthreads();
    }
    int run = s_part[tid] - sum;
    for (int i=0;i<CH;i++){
        int n = base+i;
        if (n < NN){
            int c = g_cnt[n];
            g_off[n] = run;
            g_deg[n] = (c > 0) ? (float)c : 1.0f;
            run += c;
        }
    }
}

__global__ void k_fill(const int* __restrict__ edges, const float* __restrict__ edge_attr){
    int e = blockIdx.x*blockDim.x + threadIdx.x;
    if (e < EE){
        int r = edges[e];
        int pos = atomicAdd(&g_off[r], 1);
        g_er[pos] = r;
        g_ec[pos] = edges[EE+e];
        g_ea2[pos] = ((const float2*)edge_attr)[e];
    }
}

// ------ per-layer node precompute (f32x2): A,B, vel_scale; zero aggs; reset cursor
__global__ void k_prevel(const float* __restrict__ e_w1, const float* __restrict__ e_b1,
                         const float* __restrict__ v_w1, const float* __restrict__ v_b1,
                         const float* __restrict__ v_w2, const float* __restrict__ v_b2){
    extern __shared__ float sp[];
    float* s_ew  = sp;
    float* s_vw  = sp + 8192;
    float* s_eb1 = sp + 12288;
    float* s_vb1 = sp + 12352;
    float* s_vw2 = sp + 12416;
    int tid = threadIdx.x;
    if (blockIdx.x == 0 && tid == 0) g_tile = 0;
    for (int i=tid; i<8192; i+=blockDim.x) s_ew[i] = e_w1[i];
    for (int i=tid; i<4096; i+=blockDim.x) s_vw[i] = v_w1[i];
    if (tid < 64){ s_eb1[tid]=e_b1[tid]; s_vb1[tid]=v_b1[tid]; s_vw2[tid]=v_w2[tid]; }
    __syncthreads();
    int lane = tid & 31, warp = tid >> 5;
    int j0 = 2*lane;
    int wpb = blockDim.x >> 5;
    float vb2 = v_b2[0];
    for (int n = blockIdx.x*wpb + warp; n < NN; n += gridDim.x*wpb){
        float h0 = g_h[n*H+j0], h1 = g_h[n*H+j0+1];
        ull a01 = *(const ull*)&s_eb1[j0];
        ull b01 = pack2(0.f, 0.f);
        ull t01 = *(const ull*)&s_vb1[j0];
        #pragma unroll
        for (int k=0;k<H;k++){
            float hk = __shfl_sync(0xffffffffu, (k&1)?h1:h0, k>>1);
            ull hk2 = pack2(hk, hk);
            fma2(a01, hk2, *(const ull*)&s_ew[k*H+j0]);
            fma2(b01, hk2, *(const ull*)&s_ew[(H+k)*H+j0]);
            fma2(t01, hk2, *(const ull*)&s_vw[k*H+j0]);
        }
        *(ull*)&g_A[n*H+j0] = a01;
        *(ull*)&g_B[n*H+j0] = b01;
        *(float2*)&g_magg[n*H+j0] = make_float2(0.f,0.f);
        float2 tv = unpack2(t01);
        float p = silu_f(tv.x)*s_vw2[j0] + silu_f(tv.y)*s_vw2[j0+1];
        #pragma unroll
        for (int o=16;o>0;o>>=1) p += __shfl_xor_sync(0xffffffffu, p, o);
        if (lane == 0){
            g_vel[n] = p + vb2;
            *(float4*)&g_cagg4[n*4] = make_float4(0.f,0.f,0.f,0.f);
        }
    }
}

// ------- edge kernel: warp-autonomous 16-edge subtiles (R12 config, unchanged) ----
__global__ void __launch_bounds__(256, 3)
k_edge(const float* __restrict__ e_w1, const float* __restrict__ e_w2,
       const float* __restrict__ e_b2, const float* __restrict__ c_w1,
       const float* __restrict__ c_b1, const float* __restrict__ c_w2){
    extern __shared__ float sm[];
    float* s_w2  = sm;              // 4096 (block-shared, read-only)
    float* s_c1  = sm + 4096;       // 4096
    float* s_wr  = sm + 8192;       // 64
    float* s_we0 = sm + 8256;
    float* s_we1 = sm + 8320;
    float* s_eb2 = sm + 8384;
    float* s_cb1 = sm + 8448;
    float* s_cw2 = sm + 8512;       // .. 8576
    int tid  = threadIdx.x;
    int wid  = tid >> 5, lane = tid & 31;
    float* wbp  = sm + 8576 + wid*1088;   // per-warp region (1088 floats)
    float* s_t  = wbp;                    // 64 x 16
    int*   s_r  = (int*)(wbp + 1024);     // 16
    float* s_dx = wbp + 1040;             // 16
    float* s_dy = wbp + 1056;
    float* s_dz = wbp + 1072;

    for (int i=tid; i<4096; i+=256){ s_w2[i] = e_w2[i]; s_c1[i] = c_w1[i]; }
    if (tid < 64){
        s_wr [tid] = e_w1[128*H+tid];
        s_we0[tid] = e_w1[129*H+tid];
        s_we1[tid] = e_w1[130*H+tid];
        s_eb2[tid] = e_b2[tid];
        s_cb1[tid] = c_b1[tid];
        s_cw2[tid] = c_w2[tid];
    }
    __syncthreads();

    const unsigned FM = 0xffffffffu;
    int el = lane & 15, hf = lane >> 4;   // P1: 2 lanes/edge
    int eg = lane & 3,  og = lane >> 2;   // GEMMs: 4 edges x 8 outputs per lane

    int base = 0;
    if (lane == 0) base = atomicAdd(&g_tile, 1);
    base = __shfl_sync(FM, base, 0);

    while (base < STEAL){
        #pragma unroll 1
        for (int sub=0; sub<2; sub++){
            // ---- P1: gather + first-layer pre + silu -> s_t[k][e] ----
            {
                int e = base*32 + sub*16 + el;
                int r = g_er[e], c = g_ec[e];
                float4 xr = *(const float4*)&g_x4[r*4];
                float4 xc = *(const float4*)&g_x4[c*4];
                float dx = xr.x-xc.x, dy = xr.y-xc.y, dz = xr.z-xc.z;
                float radial = dx*dx + dy*dy + dz*dz;
                float2 ea = g_ea2[e];
                const float4* Ap = (const float4*)(g_A + r*H + hf*32);
                const float4* Bp = (const float4*)(g_B + c*H + hf*32);
                int kb = hf*32;
                #pragma unroll
                for (int q=0;q<8;q++){
                    float4 av = Ap[q], bv = Bp[q];
                    int k = kb + 4*q;
                    float4 w1 = *(const float4*)&s_wr [k];
                    float4 w2 = *(const float4*)&s_we0[k];
                    float4 w3 = *(const float4*)&s_we1[k];
                    s_t[(k+0)*16+el] = silu_f(av.x + bv.x + radial*w1.x + ea.x*w2.x + ea.y*w3.x);
                    s_t[(k+1)*16+el] = silu_f(av.y + bv.y + radial*w1.y + ea.x*w2.y + ea.y*w3.y);
                    s_t[(k+2)*16+el] = silu_f(av.z + bv.z + radial*w1.z + ea.x*w2.z + ea.y*w3.z);
                    s_t[(k+3)*16+el] = silu_f(av.w + bv.w + radial*w1.w + ea.x*w2.w + ea.y*w3.w);
                }
                if (!hf){ s_r[el]=r; s_dx[el]=dx; s_dy[el]=dy; s_dz[el]=dz; }
            }
            __syncwarp();

            // ---- P2: GEMM1  M[e][j] = sum_k t[k][e] * w2[k][j] ----
            ull acc[16];
            {
                ull b0 = *(const ull*)&s_eb2[og*8+0];
                ull b1 = *(const ull*)&s_eb2[og*8+2];
                ull b2 = *(const ull*)&s_eb2[og*8+4];
                ull b3 = *(const ull*)&s_eb2[og*8+6];
                #pragma unroll
                for (int e4=0;e4<4;e4++){ acc[e4*4]=b0; acc[e4*4+1]=b1; acc[e4*4+2]=b2; acc[e4*4+3]=b3; }
                const float* tp = s_t + eg*4;
                const float* wk = s_w2 + og*8;
                #pragma unroll 8
                for (int k=0;k<64;k++){
                    float4 tv = *(const float4*)(tp + k*16);
                    ulonglong2 wa = *(const ulonglong2*)(wk + k*64);
                    ulonglong2 wb = *(const ulonglong2*)(wk + k*64 + 4);
                    ull t0 = pack2(tv.x,tv.x), t1 = pack2(tv.y,tv.y);
                    ull t2 = pack2(tv.z,tv.z), t3 = pack2(tv.w,tv.w);
                    fma2(acc[0],  t0, wa.x); fma2(acc[1],  t0, wa.y); fma2(acc[2],  t0, wb.x); fma2(acc[3],  t0, wb.y);
                    fma2(acc[4],  t1, wa.x); fma2(acc[5],  t1, wa.y); fma2(acc[6],  t1, wb.x); fma2(acc[7],  t1, wb.y);
                    fma2(acc[8],  t2, wa.x); fma2(acc[9],  t2, wa.y); fma2(acc[10], t2, wb.x); fma2(acc[11], t2, wb.y);
                    fma2(acc[12], t3, wa.x); fma2(acc[13], t3, wa.y); fma2(acc[14], t3, wb.x); fma2(acc[15], t3, wb.y);
                }
            }
            __syncwarp();

            // ---- P3: silu(M), store ms -> s_t[j][e], run-agg scatter to m_agg ----
            {
                float ms[4][8];
                #pragma unroll
                for (int e4=0;e4<4;e4++){
                    #pragma unroll
                    for (int jp=0;jp<4;jp++){
                        float2 f = unpack2(acc[e4*4+jp]);
                        ms[e4][2*jp]   = silu_f(f.x);
                        ms[e4][2*jp+1] = silu_f(f.y);
                    }
                }
                #pragma unroll
                for (int j=0;j<8;j++){
                    *(float4*)&s_t[(og*8+j)*16 + eg*4] =
                        make_float4(ms[0][j], ms[1][j], ms[2][j], ms[3][j]);
                }
                int rr[4] = {s_r[eg*4+0], s_r[eg*4+1], s_r[eg*4+2], s_r[eg*4+3]};
                int rh = 0;
                #pragma unroll
                for (int e4=1;e4<4;e4++){
                    if (rr[e4] == rr[rh]){
                        #pragma unroll
                        for (int j=0;j<8;j++) ms[rh][j] += ms[e4][j];
                    } else {
                        float* mp = &g_magg[rr[rh]*H + og*8];
                        red4(mp,   ms[rh][0], ms[rh][1], ms[rh][2], ms[rh][3]);
                        red4(mp+4, ms[rh][4], ms[rh][5], ms[rh][6], ms[rh][7]);
                        rh = e4;
                    }
                }
                float* mp = &g_magg[rr[rh]*H + og*8];
                red4(mp,   ms[rh][0], ms[rh][1], ms[rh][2], ms[rh][3]);
                red4(mp+4, ms[rh][4], ms[rh][5], ms[rh][6], ms[rh][7]);
            }
            __syncwarp();

            // ---- P4: GEMM2 + g partial; shfl-reduce over og; coord scatter ----
            {
                ull b0 = *(const ull*)&s_cb1[og*8+0];
                ull b1 = *(const ull*)&s_cb1[og*8+2];
                ull b2 = *(const ull*)&s_cb1[og*8+4];
                ull b3 = *(const ull*)&s_cb1[og*8+6];
                ull acc2[16];
                #pragma unroll
                for (int e4=0;e4<4;e4++){ acc2[e4*4]=b0; acc2[e4*4+1]=b1; acc2[e4*4+2]=b2; acc2[e4*4+3]=b3; }
                const float* tp = s_t + eg*4;
                const float* wk = s_c1 + og*8;
                #pragma unroll 8
                for (int k=0;k<64;k++){
                    float4 tv = *(const float4*)(tp + k*16);
                    ulonglong2 wa = *(const ulonglong2*)(wk + k*64);
                    ulonglong2 wb = *(const ulonglong2*)(wk + k*64 + 4);
                    ull t0 = pack2(tv.x,tv.x), t1 = pack2(tv.y,tv.y);
                    ull t2 = pack2(tv.z,tv.z), t3 = pack2(tv.w,tv.w);
                    fma2(acc2[0],  t0, wa.x); fma2(acc2[1],  t0, wa.y); fma2(acc2[2],  t0, wb.x); fma2(acc2[3],  t0, wb.y);
                    fma2(acc2[4],  t1, wa.x); fma2(acc2[5],  t1, wa.y); fma2(acc2[6],  t1, wb.x); fma2(acc2[7],  t1, wb.y);
                    fma2(acc2[8],  t2, wa.x); fma2(acc2[9],  t2, wa.y); fma2(acc2[10], t2, wb.x); fma2(acc2[11], t2, wb.y);
                    fma2(acc2[12], t3, wa.x); fma2(acc2[13], t3, wa.y); fma2(acc2[14], t3, wb.x); fma2(acc2[15], t3, wb.y);
                }
                float gp[4];
                #pragma unroll
                for (int e4=0;e4<4;e4++){
                    float s = 0.f;
                    #pragma unroll
                    for (int jp=0;jp<4;jp++){
                        float2 f = unpack2(acc2[e4*4+jp]);
                        s += silu_f(f.x)*s_cw2[og*8+2*jp] + silu_f(f.y)*s_cw2[og*8+2*jp+1];
                    }
                    gp[e4] = s;
                }
                #pragma unroll
                for (int off=4; off<32; off<<=1){
                    #pragma unroll
                    for (int e4=0;e4<4;e4++)
                        gp[e4] += __shfl_xor_sync(FM, gp[e4], off);
                }
                if (og == 0){
                    int i0 = eg*4;
                    int rcur = s_r[i0];
                    float cx = s_dx[i0]*gp[0], cy = s_dy[i0]*gp[0], cz = s_dz[i0]*gp[0];
                    #pragma unroll
                    for (int i=1;i<4;i++){
                        int ri = s_r[i0+i];
                        float gx = s_dx[i0+i]*gp[i], gy = s_dy[i0+i]*gp[i], gz = s_dz[i0+i]*gp[i];
                        if (ri == rcur){ cx += gx; cy += gy; cz += gz; }
                        else {
                            red4(&g_cagg4[rcur*4], cx, cy, cz, 0.f);
                            rcur = ri; cx = gx; cy = gy; cz = gz;
                        }
                    }
                    red4(&g_cagg4[rcur*4], cx, cy, cz, 0.f);
                }
            }
            __syncwarp();
        }
        if (lane == 0) base = atomicAdd(&g_tile, 1);
        base = __shfl_sync(FM, base, 0);
    }
}

// -------- fused node MLP + state update (f32x2); last layer writes output ---------
__global__ void k_node(const float* __restrict__ n_w1, const float* __restrict__ n_b1,
                       const float* __restrict__ n_w2, const float* __restrict__ n_b2,
                       float* __restrict__ out, int last){
    extern __shared__ float sn[];
    float* s_w1 = sn;
    float* s_w2 = sn + 8192;
    float* s_b1 = sn + 12288;
    float* s_b2 = sn + 12352;
    int tid = threadIdx.x;
    for (int i=tid; i<8192; i+=blockDim.x) s_w1[i] = n_w1[i];
    for (int i=tid; i<4096; i+=blockDim.x) s_w2[i] = n_w2[i];
    if (tid < 64){ s_b1[tid]=n_b1[tid]; s_b2[tid]=n_b2[tid]; }
    __syncthreads();
    int lane = tid & 31, warp = tid >> 5;
    int j0 = 2*lane;
    int wpb = blockDim.x >> 5;
    for (int n = blockIdx.x*wpb + warp; n < NN; n += gridDim.x*wpb){
        float h0 = g_h[n*H+j0],    h1 = g_h[n*H+j0+1];
        float m0 = g_magg[n*H+j0], m1 = g_magg[n*H+j0+1];
        ull u01 = *(const ull*)&s_b1[j0];
        #pragma unroll
        for (int k=0;k<H;k++){
            float hk = __shfl_sync(0xffffffffu, (k&1)?h1:h0, k>>1);
            float mk = __shfl_sync(0xffffffffu, (k&1)?m1:m0, k>>1);
            fma2(u01, pack2(hk,hk), *(const ull*)&s_w1[k*H+j0]);
            fma2(u01, pack2(mk,mk), *(const ull*)&s_w1[(H+k)*H+j0]);
        }
        float2 uv = unpack2(u01);
        float u0 = silu_f(uv.x), u1 = silu_f(uv.y);
        ull a01 = *(const ull*)&s_b2[j0];
        #pragma unroll
        for (int k=0;k<H;k++){
            float uk = __shfl_sync(0xffffffffu, (k&1)?u1:u0, k>>1);
            fma2(a01, pack2(uk,uk), *(const ull*)&s_w2[k*H+j0]);
        }
        float2 av = unpack2(a01);
        float hn0 = 2.f*h0 + av.x, hn1 = 2.f*h1 + av.y;
        *(float2*)&g_h[n*H+j0] = make_float2(hn0, hn1);
        float vn = 0.f, xn = 0.f;
        if (lane < 3){
            float dg = g_deg[n];
            float cm = g_cagg4[n*4+lane] / dg;
            float vi = g_v4[n*4+lane];
            vn = vi + cm + g_vel[n]*vi;
            g_v4[n*4+lane] = vn;
            xn = g_x4[n*4+lane] + vn;
            g_x4[n*4+lane] = xn;
        }
        if (last){
            *(float2*)&out[NN*3 + n*H + j0] = make_float2(hn0, hn1);
            if (lane < 3){
                out[n*3 + lane] = xn;
                out[NN*3 + NN*H + n*3 + lane] = vn;
            }
        }
    }
}

extern "C" void kernel_launch(void* const* d_in, const int* in_sizes, int n_in,
                              void* d_out, int out_size){
    const float* his  = (const float*)d_in[0];
    const float* x    = (const float*)d_in[1];
    const float* v    = (const float*)d_in[2];
    const float* edge_attr = (const float*)d_in[3];
    const int*   edges= (const int*)  d_in[4];
    const float* emb_w= (const float*)d_in[5];
    const float* emb_b= (const float*)d_in[6];
    const float* e_w1 = (const float*)d_in[7];
    const float* e_b1 = (const float*)d_in[8];
    const float* e_w2 = (const float*)d_in[9];
    const float* e_b2 = (const float*)d_in[10];
    const float* c_w1 = (const float*)d_in[11];
    const float* c_b1 = (const float*)d_in[12];
    const float* c_w2 = (const float*)d_in[13];
    const float* n_w1 = (const float*)d_in[14];
    const float* n_b1 = (const float*)d_in[15];
    const float* n_w2 = (const float*)d_in[16];
    const float* n_b2 = (const float*)d_in[17];
    const float* v_w1 = (const float*)d_in[18];
    const float* v_b1 = (const float*)d_in[19];
    const float* v_w2 = (const float*)d_in[20];
    const float* v_b2 = (const float*)d_in[21];

    const int PREVEL_SMEM = 12480*4;
    const int NODE_SMEM   = 12416*4;
    const int EDGE_SMEM   = 17280*4;   // 69120 B
    cudaFuncSetAttribute(k_prevel, cudaFuncAttributeMaxDynamicSharedMemorySize, PREVEL_SMEM);
    cudaFuncSetAttribute(k_node,   cudaFuncAttributeMaxDynamicSharedMemorySize, NODE_SMEM);
    cudaFuncSetAttribute(k_edge,   cudaFuncAttributeMaxDynamicSharedMemorySize, EDGE_SMEM);

    k_init<<<(NN*H+255)/256, 256>>>(his, emb_w, emb_b, x, v);
    k_deg<<<(EE+255)/256, 256>>>(edges);
    k_scan<<<1, 1024>>>();
    k_fill<<<(EE+255)/256, 256>>>(edges, edge_attr);

    const int gn = 444;
    const int ge = 444;    // 148 SMs x 3 blocks; 24 autonomous warps/SM

    for (int l=0; l<3; l++){
        k_prevel<<<gn, 256, PREVEL_SMEM>>>(e_w1, e_b1, v_w1, v_b1, v_w2, v_b2);
        k_edge<<<ge, 256, EDGE_SMEM>>>(e_w1, e_w2, e_b2, c_w1, c_b1, c_w2);
        k_node<<<gn, 256, NODE_SMEM>>>(n_w1, n_b1, n_w2, n_b2,
                                       (float*)d_out, (l == 2) ? 1 : 0);
    }
}

// round 15
// speedup vs baseline: 1.5052x; 1.2879x over previous
#include <cuda_runtime.h>

#define NN 50000
#define EE 1600000
#define H  64
#define STEAL (EE/32)   // 50000 steal units of 32 edges (2 x 16-edge subtiles)

typedef unsigned long long ull;

// ---------------- scratch (device globals; no allocation allowed) ----------------
__device__ float g_h[NN*H];
__device__ float g_A[NN*H];      // h@Wa + e_b1
__device__ float g_B[NN*H];      // h@Wb
__device__ float g_magg[NN*H];   // segment-summed messages
__device__ float g_cagg4[NN*4];  // segment-summed coord updates (padded)
__device__ float g_vel[NN];      // vel_scale
__device__ float g_deg[NN];      // clipped out-degree (float)
__device__ int   g_cnt[NN];      // raw out-degree
__device__ int   g_off[NN];      // fill cursors
__device__ float g_x4[NN*4];     // padded coords
__device__ float g_v4[NN*4];     // padded velocities
__device__ int   g_tile;         // dynamic steal cursor
// r-sorted edge arrays
__device__ int    g_er[EE];
__device__ int    g_ec[EE];
__device__ float2 g_ea2[EE];

__device__ __forceinline__ float silu_f(float x){
    float th;
    asm("tanh.approx.f32 %0, %1;" : "=f"(th) : "f"(0.5f*x));
    return 0.5f*x*th + 0.5f*x;
}
__device__ __forceinline__ ull pack2(float x, float y){
    ull r; asm("mov.b64 %0, {%1,%2};" : "=l"(r) : "f"(x), "f"(y)); return r;
}
__device__ __forceinline__ float2 unpack2(ull p){
    float2 r; asm("mov.b64 {%0,%1}, %2;" : "=f"(r.x), "=f"(r.y) : "l"(p)); return r;
}
__device__ __forceinline__ void fma2(ull& d, ull a, ull b){
    asm("fma.rn.f32x2 %0, %1, %2, %0;" : "+l"(d) : "l"(a), "l"(b));
}
__device__ __forceinline__ void red4(float* p, float a, float b, float c, float d){
    asm volatile("red.global.add.v4.f32 [%0], {%1,%2,%3,%4};"
                 :: "l"(p), "f"(a), "f"(b), "f"(c), "f"(d) : "memory");
}
__device__ __forceinline__ void red2(float* p, float a, float b){
    asm volatile("red.global.add.v2.f32 [%0], {%1,%2};"
                 :: "l"(p), "f"(a), "f"(b) : "memory");
}
__device__ __forceinline__ unsigned to_tf32(float f){
    unsigned r; asm("cvt.rna.tf32.f32 %0, %1;" : "=r"(r) : "f"(f)); return r;
}
// m16n8k8 tf32 MMA: D += A@B (A row-major 16x8, B col-major 8x8, fp32 accum)
__device__ __forceinline__ void mma8(float& d0, float& d1, float& d2, float& d3,
                                     unsigned a0, unsigned a1, unsigned a2, unsigned a3,
                                     ull b01){
    unsigned b0 = (unsigned)b01, b1 = (unsigned)(b01 >> 32);
    asm("mma.sync.aligned.m16n8k8.row.col.f32.tf32.tf32.f32 "
        "{%0,%1,%2,%3}, {%4,%5,%6,%7}, {%8,%9}, {%0,%1,%2,%3};"
        : "+f"(d0), "+f"(d1), "+f"(d2), "+f"(d3)
        : "r"(a0), "r"(a1), "r"(a2), "r"(a3), "r"(b0), "r"(b1));
}

// ---------------- init ------------------------------------------------------------
__global__ void k_init(const float* __restrict__ his, const float* __restrict__ emb_w,
                       const float* __restrict__ emb_b, const float* __restrict__ x,
                       const float* __restrict__ v){
    int idx = blockIdx.x*blockDim.x + threadIdx.x;
    if (idx < NN*H){
        int n = idx >> 6, j = idx & 63;
        float acc = emb_b[j];
        #pragma unroll
        for (int k=0;k<16;k++) acc += his[n*16+k]*emb_w[k*H+j];
        g_h[idx] = acc;
    }
    if (idx < NN){
        g_x4[idx*4+0]=x[idx*3+0]; g_x4[idx*4+1]=x[idx*3+1]; g_x4[idx*4+2]=x[idx*3+2]; g_x4[idx*4+3]=0.f;
        g_v4[idx*4+0]=v[idx*3+0]; g_v4[idx*4+1]=v[idx*3+1]; g_v4[idx*4+2]=v[idx*3+2]; g_v4[idx*4+3]=0.f;
        g_cnt[idx] = 0;
    }
}

__global__ void k_deg(const int* __restrict__ edges){
    int e = blockIdx.x*blockDim.x + threadIdx.x;
    if (e < EE) atomicAdd(&g_cnt[edges[e]], 1);
}

// single-block exclusive scan over g_cnt -> g_off; also g_deg = max(cnt,1)
__global__ void k_scan(){
    __shared__ int s_part[1024];
    int tid = threadIdx.x;
    const int CH = (NN + 1023)/1024;
    int base = tid*CH;
    int sum = 0;
    #pragma unroll 7
    for (int i=0;i<CH;i++){ int n=base+i; if(n<NN) sum += g_cnt[n]; }
    s_part[tid] = sum;
    __syncthreads();
    for (int off=1; off<1024; off<<=1){
        int t = (tid >= off) ? s_part[tid-off] : 0;
        __syncthreads();
        s_part[tid] += t;
        __syncthreads();
    }
    int run = s_part[tid] - sum;
    for (int i=0;i<CH;i++){
        int n = base+i;
        if (n < NN){
            int c = g_cnt[n];
            g_off[n] = run;
            g_deg[n] = (c > 0) ? (float)c : 1.0f;
            run += c;
        }
    }
}

__global__ void k_fill(const int* __restrict__ edges, const float* __restrict__ edge_attr){
    int e = blockIdx.x*blockDim.x + threadIdx.x;
    if (e < EE){
        int r = edges[e];
        int pos = atomicAdd(&g_off[r], 1);
        g_er[pos] = r;
        g_ec[pos] = edges[EE+e];
        g_ea2[pos] = ((const float2*)edge_attr)[e];
    }
}

// ------ per-layer node precompute (f32x2): A,B, vel_scale; zero aggs; reset cursor
__global__ void k_prevel(const float* __restrict__ e_w1, const float* __restrict__ e_b1,
                         const float* __restrict__ v_w1, const float* __restrict__ v_b1,
                         const float* __restrict__ v_w2, const float* __restrict__ v_b2){
    extern __shared__ float sp[];
    float* s_ew  = sp;
    float* s_vw  = sp + 8192;
    float* s_eb1 = sp + 12288;
    float* s_vb1 = sp + 12352;
    float* s_vw2 = sp + 12416;
    int tid = threadIdx.x;
    if (blockIdx.x == 0 && tid == 0) g_tile = 0;
    for (int i=tid; i<8192; i+=blockDim.x) s_ew[i] = e_w1[i];
    for (int i=tid; i<4096; i+=blockDim.x) s_vw[i] = v_w1[i];
    if (tid < 64){ s_eb1[tid]=e_b1[tid]; s_vb1[tid]=v_b1[tid]; s_vw2[tid]=v_w2[tid]; }
    __syncthreads();
    int lane = tid & 31, warp = tid >> 5;
    int j0 = 2*lane;
    int wpb = blockDim.x >> 5;
    float vb2 = v_b2[0];
    for (int n = blockIdx.x*wpb + warp; n < NN; n += gridDim.x*wpb){
        float h0 = g_h[n*H+j0], h1 = g_h[n*H+j0+1];
        ull a01 = *(const ull*)&s_eb1[j0];
        ull b01 = pack2(0.f, 0.f);
        ull t01 = *(const ull*)&s_vb1[j0];
        #pragma unroll
        for (int k=0;k<H;k++){
            float hk = __shfl_sync(0xffffffffu, (k&1)?h1:h0, k>>1);
            ull hk2 = pack2(hk, hk);
            fma2(a01, hk2, *(const ull*)&s_ew[k*H+j0]);
            fma2(b01, hk2, *(const ull*)&s_ew[(H+k)*H+j0]);
            fma2(t01, hk2, *(const ull*)&s_vw[k*H+j0]);
        }
        *(ull*)&g_A[n*H+j0] = a01;
        *(ull*)&g_B[n*H+j0] = b01;
        *(float2*)&g_magg[n*H+j0] = make_float2(0.f,0.f);
        float2 tv = unpack2(t01);
        float p = silu_f(tv.x)*s_vw2[j0] + silu_f(tv.y)*s_vw2[j0+1];
        #pragma unroll
        for (int o=16;o>0;o>>=1) p += __shfl_xor_sync(0xffffffffu, p, o);
        if (lane == 0){
            g_vel[n] = p + vb2;
            *(float4*)&g_cagg4[n*4] = make_float4(0.f,0.f,0.f,0.f);
        }
    }
}

// ------- edge kernel: warp-autonomous 16-edge subtiles, tf32 mma.sync GEMMs -------
__global__ void __launch_bounds__(256, 3)
k_edge(const float* __restrict__ e_w1, const float* __restrict__ e_w2,
       const float* __restrict__ e_b2, const float* __restrict__ c_w1,
       const float* __restrict__ c_b1, const float* __restrict__ c_w2){
    extern __shared__ float sm[];
    ull*   w2p   = (ull*)sm;         // 2048 ull = 4096 floats (packed B frags, GEMM1)
    ull*   c1p   = (ull*)(sm + 4096);// 2048 ull (GEMM2)
    float* s_wr  = sm + 8192;        // 64
    float* s_we0 = sm + 8256;
    float* s_we1 = sm + 8320;
    float* s_eb2 = sm + 8384;
    float* s_cb1 = sm + 8448;
    float* s_cw2 = sm + 8512;        // .. 8576
    int tid  = threadIdx.x;
    int wid  = tid >> 5, lane = tid & 31;
    float* wbp  = sm + 8576 + wid*1088;   // per-warp region (1088 floats)
    float* s_t  = wbp;                    // 64 x 16  (tf32 bits as float)
    int*   s_r  = (int*)(wbp + 1024);     // 16
    float* s_dx = wbp + 1040;             // 16
    float* s_dy = wbp + 1056;
    float* s_dz = wbp + 1072;
    // total smem: 8576 + 8*1088 = 17280 floats = 69120 B

    // pack weights into per-(ktile,ntile) lane-ordered tf32 B fragments
    for (int idx=tid; idx<2048; idx+=256){
        int tile = idx >> 5, vl = idx & 31;
        int kt = tile >> 3, nt = tile & 7;
        int tg = vl & 3,  gd = vl >> 2;
        int k0 = kt*8 + tg, j = nt*8 + gd;
        unsigned b0 = to_tf32(e_w2[k0*64 + j]);
        unsigned b1 = to_tf32(e_w2[(k0+4)*64 + j]);
        w2p[idx] = ((ull)b1 << 32) | (ull)b0;
        b0 = to_tf32(c_w1[k0*64 + j]);
        b1 = to_tf32(c_w1[(k0+4)*64 + j]);
        c1p[idx] = ((ull)b1 << 32) | (ull)b0;
    }
    if (tid < 64){
        s_wr [tid] = e_w1[128*H+tid];
        s_we0[tid] = e_w1[129*H+tid];
        s_we1[tid] = e_w1[130*H+tid];
        s_eb2[tid] = e_b2[tid];
        s_cb1[tid] = c_b1[tid];
        s_cw2[tid] = c_w2[tid];
    }
    __syncthreads();

    const unsigned FM = 0xffffffffu;
    int el = lane & 15, hf = lane >> 4;   // P1: 2 lanes/edge
    int tig = lane & 3, gid = lane >> 2;  // mma fragment coords

    int base = 0;
    if (lane == 0) base = atomicAdd(&g_tile, 1);
    base = __shfl_sync(FM, base, 0);

    while (base < STEAL){
        #pragma unroll 1
        for (int sub=0; sub<2; sub++){
            // ---- P1: gather + first-layer pre + silu -> tf32 s_t[k][e] ----
            {
                int e = base*32 + sub*16 + el;
                int r = g_er[e], c = g_ec[e];
                float4 xr = *(const float4*)&g_x4[r*4];
                float4 xc = *(const float4*)&g_x4[c*4];
                float dx = xr.x-xc.x, dy = xr.y-xc.y, dz = xr.z-xc.z;
                float radial = dx*dx + dy*dy + dz*dz;
                float2 ea = g_ea2[e];
                const float4* Ap = (const float4*)(g_A + r*H + hf*32);
                const float4* Bp = (const float4*)(g_B + c*H + hf*32);
                int kb = hf*32;
                #pragma unroll
                for (int q=0;q<8;q++){
                    float4 av = Ap[q], bv = Bp[q];
                    int k = kb + 4*q;
                    float4 w1 = *(const float4*)&s_wr [k];
                    float4 w2 = *(const float4*)&s_we0[k];
                    float4 w3 = *(const float4*)&s_we1[k];
                    s_t[(k+0)*16+el] = __uint_as_float(to_tf32(
                        silu_f(av.x + bv.x + radial*w1.x + ea.x*w2.x + ea.y*w3.x)));
                    s_t[(k+1)*16+el] = __uint_as_float(to_tf32(
                        silu_f(av.y + bv.y + radial*w1.y + ea.x*w2.y + ea.y*w3.y)));
                    s_t[(k+2)*16+el] = __uint_as_float(to_tf32(
                        silu_f(av.z + bv.z + radial*w1.z + ea.x*w2.z + ea.y*w3.z)));
                    s_t[(k+3)*16+el] = __uint_as_float(to_tf32(
                        silu_f(av.w + bv.w + radial*w1.w + ea.x*w2.w + ea.y*w3.w)));
                }
                if (!hf){ s_r[el]=r; s_dx[el]=dx; s_dy[el]=dy; s_dz[el]=dz; }
            }
            __syncwarp();

            // ---- load A fragments for GEMM1 (t, all 8 k-tiles) ----
            unsigned af[32];
            #pragma unroll
            for (int kt=0;kt<8;kt++){
                const float* b = s_t + (kt*8 + tig)*16 + gid;
                af[kt*4+0] = __float_as_uint(b[0]);
                af[kt*4+1] = __float_as_uint(b[8]);
                af[kt*4+2] = __float_as_uint(b[64]);
                af[kt*4+3] = __float_as_uint(b[72]);
            }
            __syncwarp();

            int r0 = s_r[gid], r1 = s_r[gid+8];

            // ---- GEMM1 (8 n-tiles): M = t @ e_w2 + b; silu; scatter; store tf32 --
            #pragma unroll
            for (int nt=0;nt<8;nt++){
                int c0 = nt*8 + 2*tig;
                float d0 = s_eb2[c0], d1 = s_eb2[c0+1];
                float d2 = d0, d3 = d1;
                #pragma unroll
                for (int kt=0;kt<8;kt++)
                    mma8(d0,d1,d2,d3, af[kt*4],af[kt*4+1],af[kt*4+2],af[kt*4+3],
                         w2p[(kt*8+nt)*32 + lane]);
                float m0 = silu_f(d0), m1 = silu_f(d1);
                float m2 = silu_f(d2), m3 = silu_f(d3);
                red2(&g_magg[r0*H + c0], m0, m1);
                red2(&g_magg[r1*H + c0], m2, m3);
                s_t[ c0   *16 + gid  ] = __uint_as_float(to_tf32(m0));
                s_t[(c0+1)*16 + gid  ] = __uint_as_float(to_tf32(m1));
                s_t[ c0   *16 + gid+8] = __uint_as_float(to_tf32(m2));
                s_t[(c0+1)*16 + gid+8] = __uint_as_float(to_tf32(m3));
            }
            __syncwarp();

            // ---- load A fragments for GEMM2 (m) ----
            #pragma unroll
            for (int kt=0;kt<8;kt++){
                const float* b = s_t + (kt*8 + tig)*16 + gid;
                af[kt*4+0] = __float_as_uint(b[0]);
                af[kt*4+1] = __float_as_uint(b[8]);
                af[kt*4+2] = __float_as_uint(b[64]);
                af[kt*4+3] = __float_as_uint(b[72]);
            }
            __syncwarp();

            // ---- GEMM2: U = m @ c_w1 + cb1; g = sum silu(U)*cw2 ----
            float gp0 = 0.f, gp1 = 0.f;
            #pragma unroll
            for (int nt=0;nt<8;nt++){
                int c0 = nt*8 + 2*tig;
                float d0 = s_cb1[c0], d1 = s_cb1[c0+1];
                float d2 = d0, d3 = d1;
                #pragma unroll
                for (int kt=0;kt<8;kt++)
                    mma8(d0,d1,d2,d3, af[kt*4],af[kt*4+1],af[kt*4+2],af[kt*4+3],
                         c1p[(kt*8+nt)*32 + lane]);
                float w0 = s_cw2[c0], w1 = s_cw2[c0+1];
                gp0 += silu_f(d0)*w0 + silu_f(d1)*w1;
                gp1 += silu_f(d2)*w0 + silu_f(d3)*w1;
            }
            gp0 += __shfl_xor_sync(FM, gp0, 1);
            gp0 += __shfl_xor_sync(FM, gp0, 2);
            gp1 += __shfl_xor_sync(FM, gp1, 1);
            gp1 += __shfl_xor_sync(FM, gp1, 2);
            if (tig == 0){
                float cx0 = s_dx[gid]*gp0,   cy0 = s_dy[gid]*gp0,   cz0 = s_dz[gid]*gp0;
                float cx1 = s_dx[gid+8]*gp1, cy1 = s_dy[gid+8]*gp1, cz1 = s_dz[gid+8]*gp1;
                if (r0 == r1){
                    red4(&g_cagg4[r0*4], cx0+cx1, cy0+cy1, cz0+cz1, 0.f);
                } else {
                    red4(&g_cagg4[r0*4], cx0, cy0, cz0, 0.f);
                    red4(&g_cagg4[r1*4], cx1, cy1, cz1, 0.f);
                }
            }
            __syncwarp();   // protect s_t/s_r before next subtile's P1
        }
        if (lane == 0) base = atomicAdd(&g_tile, 1);
        base = __shfl_sync(FM, base, 0);
    }
}

// -------- fused node MLP + state update (f32x2); last layer writes output ---------
__global__ void k_node(const float* __restrict__ n_w1, const float* __restrict__ n_b1,
                       const float* __restrict__ n_w2, const float* __restrict__ n_b2,
                       float* __restrict__ out, int last){
    extern __shared__ float sn[];
    float* s_w1 = sn;
    float* s_w2 = sn + 8192;
    float* s_b1 = sn + 12288;
    float* s_b2 = sn + 12352;
    int tid = threadIdx.x;
    for (int i=tid; i<8192; i+=blockDim.x) s_w1[i] = n_w1[i];
    for (int i=tid; i<4096; i+=blockDim.x) s_w2[i] = n_w2[i];
    if (tid < 64){ s_b1[tid]=n_b1[tid]; s_b2[tid]=n_b2[tid]; }
    __syncthreads();
    int lane = tid & 31, warp = tid >> 5;
    int j0 = 2*lane;
    int wpb = blockDim.x >> 5;
    for (int n = blockIdx.x*wpb + warp; n < NN; n += gridDim.x*wpb){
        float h0 = g_h[n*H+j0],    h1 = g_h[n*H+j0+1];
        float m0 = g_magg[n*H+j0], m1 = g_magg[n*H+j0+1];
        ull u01 = *(const ull*)&s_b1[j0];
        #pragma unroll
        for (int k=0;k<H;k++){
            float hk = __shfl_sync(0xffffffffu, (k&1)?h1:h0, k>>1);
            float mk = __shfl_sync(0xffffffffu, (k&1)?m1:m0, k>>1);
            fma2(u01, pack2(hk,hk), *(const ull*)&s_w1[k*H+j0]);
            fma2(u01, pack2(mk,mk), *(const ull*)&s_w1[(H+k)*H+j0]);
        }
        float2 uv = unpack2(u01);
        float u0 = silu_f(uv.x), u1 = silu_f(uv.y);
        ull a01 = *(const ull*)&s_b2[j0];
        #pragma unroll
        for (int k=0;k<H;k++){
            float uk = __shfl_sync(0xffffffffu, (k&1)?u1:u0, k>>1);
            fma2(a01, pack2(uk,uk), *(const ull*)&s_w2[k*H+j0]);
        }
        float2 av = unpack2(a01);
        float hn0 = 2.f*h0 + av.x, hn1 = 2.f*h1 + av.y;
        *(float2*)&g_h[n*H+j0] = make_float2(hn0, hn1);
        float vn = 0.f, xn = 0.f;
        if (lane < 3){
            float dg = g_deg[n];
            float cm = g_cagg4[n*4+lane] / dg;
            float vi = g_v4[n*4+lane];
            vn = vi + cm + g_vel[n]*vi;
            g_v4[n*4+lane] = vn;
            xn = g_x4[n*4+lane] + vn;
            g_x4[n*4+lane] = xn;
        }
        if (last){
            *(float2*)&out[NN*3 + n*H + j0] = make_float2(hn0, hn1);
            if (lane < 3){
                out[n*3 + lane] = xn;
                out[NN*3 + NN*H + n*3 + lane] = vn;
            }
        }
    }
}

extern "C" void kernel_launch(void* const* d_in, const int* in_sizes, int n_in,
                              void* d_out, int out_size){
    const float* his  = (const float*)d_in[0];
    const float* x    = (const float*)d_in[1];
    const float* v    = (const float*)d_in[2];
    const float* edge_attr = (const float*)d_in[3];
    const int*   edges= (const int*)  d_in[4];
    const float* emb_w= (const float*)d_in[5];
    const float* emb_b= (const float*)d_in[6];
    const float* e_w1 = (const float*)d_in[7];
    const float* e_b1 = (const float*)d_in[8];
    const float* e_w2 = (const float*)d_in[9];
    const float* e_b2 = (const float*)d_in[10];
    const float* c_w1 = (const float*)d_in[11];
    const float* c_b1 = (const float*)d_in[12];
    const float* c_w2 = (const float*)d_in[13];
    const float* n_w1 = (const float*)d_in[14];
    const float* n_b1 = (const float*)d_in[15];
    const float* n_w2 = (const float*)d_in[16];
    const float* n_b2 = (const float*)d_in[17];
    const float* v_w1 = (const float*)d_in[18];
    const float* v_b1 = (const float*)d_in[19];
    const float* v_w2 = (const float*)d_in[20];
    const float* v_b2 = (const float*)d_in[21];

    const int PREVEL_SMEM = 12480*4;
    const int NODE_SMEM   = 12416*4;
    const int EDGE_SMEM   = 17280*4;   // 69120 B
    cudaFuncSetAttribute(k_prevel, cudaFuncAttributeMaxDynamicSharedMemorySize, PREVEL_SMEM);
    cudaFuncSetAttribute(k_node,   cudaFuncAttributeMaxDynamicSharedMemorySize, NODE_SMEM);
    cudaFuncSetAttribute(k_edge,   cudaFuncAttributeMaxDynamicSharedMemorySize, EDGE_SMEM);

    k_init<<<(NN*H+255)/256, 256>>>(his, emb_w, emb_b, x, v);
    k_deg<<<(EE+255)/256, 256>>>(edges);
    k_scan<<<1, 1024>>>();
    k_fill<<<(EE+255)/256, 256>>>(edges, edge_attr);

    const int gn = 444;
    const int ge = 444;    // 148 SMs x 3 blocks; 24 autonomous warps/SM

    for (int l=0; l<3; l++){
        k_prevel<<<gn, 256, PREVEL_SMEM>>>(e_w1, e_b1, v_w1, v_b1, v_w2, v_b2);
        k_edge<<<ge, 256, EDGE_SMEM>>>(e_w1, e_w2, e_b2, c_w1, c_b1, c_w2);
        k_node<<<gn, 256, NODE_SMEM>>>(n_w1, n_b1, n_w2, n_b2,
                                       (float*)d_out, (l == 2) ? 1 : 0);
    }
}